// round 15
// baseline (speedup 1.0000x reference)
#include <cuda_runtime.h>
#include <math.h>

typedef unsigned long long ull;

#define THREADS 256
#define NPTS 4096
#define HALF (NPTS / 2)          // 2048 opponents per tile-half
#define NPAIRS_H (HALF / 2)      // 1024 pairs
#define BATCH 2
#define BN (BATCH * NPTS)        // 8192 queries per side
#define QPB 16                   // queries per block
#define SUBS 16                  // threads per query
#define PCHUNK_H (NPAIRS_H / SUBS)   // 64 pairs per thread
#define INV_TAU 50.0f
#define NKEXP (-72.13475204444817f)  // -1/(TAU*ln2)
#define INV_NK (-0.013862943611198906f)   // 1/NKEXP
#define COEF (1.0f / (float)(BATCH * NPTS))
#define PW_BLOCKS 448

// half-tile: 3 ull planes (x,y,z pairs) = 24KB
#define TILE_BYTES (3 * NPAIRS_H * sizeof(ull))

// ---- scalar HW approximations ----
__device__ __forceinline__ float ex2(float x) {
    float y; asm("ex2.approx.ftz.f32 %0, %1;" : "=f"(y) : "f"(x)); return y;
}
__device__ __forceinline__ float rsq(float x) {
    float y; asm("rsqrt.approx.f32 %0, %1;" : "=f"(y) : "f"(x)); return y;
}
__device__ __forceinline__ float sqa(float x) {
    float y; asm("sqrt.approx.ftz.f32 %0, %1;" : "=f"(y) : "f"(x)); return y;
}
__device__ __forceinline__ float rcp(float x) {
    float y; asm("rcp.approx.ftz.f32 %0, %1;" : "=f"(y) : "f"(x)); return y;
}

// ---- packed f32x2 (Blackwell sm_100+) ----
__device__ __forceinline__ ull f2pack(float lo, float hi) {
    ull v; asm("mov.b64 %0, {%1, %2};" : "=l"(v) : "f"(lo), "f"(hi)); return v;
}
__device__ __forceinline__ void f2unpack(ull v, float& lo, float& hi) {
    asm("mov.b64 {%0, %1}, %2;" : "=f"(lo), "=f"(hi) : "l"(v));
}
__device__ __forceinline__ ull f2add(ull a, ull b) {
    ull d; asm("add.rn.f32x2 %0, %1, %2;" : "=l"(d) : "l"(a), "l"(b)); return d;
}
__device__ __forceinline__ ull f2mul(ull a, ull b) {
    ull d; asm("mul.rn.f32x2 %0, %1, %2;" : "=l"(d) : "l"(a), "l"(b)); return d;
}
__device__ __forceinline__ ull f2fma(ull a, ull b, ull c) {
    ull d; asm("fma.rn.f32x2 %0, %1, %2, %3;" : "=l"(d) : "l"(a), "l"(b), "l"(c)); return d;
}

// ---- partials: every slot written unconditionally (no init, no atomics) ----
__device__ float g_pw[4][PW_BLOCKS];
__device__ float g_Zp[2][2][BN];
__device__ float g_Sup[2][2][BN];
__device__ float g_mnp[2][2][BN];
__device__ __align__(16) float2 g_stats[2][BN];     // (COEF/Z, 1+T/tau) both sides
__device__ __align__(8) float g_csx[BN];            // col stats, pair-adjacent (linear m)
__device__ __align__(8) float g_csy[BN];
__device__ float g_sf_mn[64];
__device__ float g_sf_T[64];
__device__ float g_gp[2][3][BN];
__device__ float g_gf[32];

__device__ __forceinline__ float warpSum(float v) {
#pragma unroll
    for (int o = 16; o > 0; o >>= 1) v += __shfl_xor_sync(0xffffffffu, v, o);
    return v;
}

__device__ __forceinline__ float blockSum(float v, float* sh) {
    __syncthreads();
    v = warpSum(v);
    int w = threadIdx.x >> 5, l = threadIdx.x & 31;
    if (l == 0) sh[w] = v;
    __syncthreads();
    if (threadIdx.x == 0) {
        float x = 0.f;
#pragma unroll
        for (int i = 0; i < THREADS / 32; i++) x += sh[i];
        sh[0] = x;
    }
    __syncthreads();
    return sh[0];
}

// ---------------- pointwise losses over B*P points ----------------
__global__ void pointwise_kernel(const float* __restrict__ sp, const float* __restrict__ st,
                                 const float* __restrict__ un, const float* __restrict__ op,
                                 const float* __restrict__ ot, const float* __restrict__ na_,
                                 const float* __restrict__ nb_, int n) {
    float s_l1 = 0.f, s_bce = 0.f, s_unc = 0.f, s_nrm = 0.f;
    for (int i = blockIdx.x * blockDim.x + threadIdx.x; i < n; i += gridDim.x * blockDim.x) {
        s_l1 += fabsf(sp[i] - st[i]);
        float p = op[i], t = ot[i];
        s_bce -= t * __logf(p) + (1.f - t) * __logf(1.f - p);
        float u = un[i];
        s_unc += u * (1.f - u);
        float ax = na_[3 * i], ay = na_[3 * i + 1], az = na_[3 * i + 2];
        float bx = nb_[3 * i], by = nb_[3 * i + 1], bz = nb_[3 * i + 2];
        float nna2 = fmaf(ax, ax, fmaf(ay, ay, az * az));
        float nnb2 = fmaf(bx, bx, fmaf(by, by, bz * bz));
        float inv = rsq(fmaxf(nna2, 1e-16f)) * rsq(fmaxf(nnb2, 1e-16f));
        float cs = fmaf(ax, bx, fmaf(ay, by, az * bz)) * inv;
        s_nrm += 1.f - cs;
    }
    __shared__ float sh[8];
    float v;
    v = blockSum(s_l1, sh);  if (threadIdx.x == 0) g_pw[0][blockIdx.x] = v;
    v = blockSum(s_bce, sh); if (threadIdx.x == 0) g_pw[1][blockIdx.x] = v;
    v = blockSum(s_unc, sh); if (threadIdx.x == 0) g_pw[2][blockIdx.x] = v;
    v = blockSum(s_nrm, sh); if (threadIdx.x == 0) g_pw[3][blockIdx.x] = v;
}

// pack a 2048-point half into pair planes: xx=(xA,xB), yy=(yA,yB), zz=(zA,zB)
__device__ __forceinline__ void fill_pairs(ull* xx, ull* yy, ull* zz,
                                           const float* __restrict__ base, int t) {
#pragma unroll
    for (int j = 0; j < NPAIRS_H / THREADS; j++) {   // 4
        int p = t + j * THREADS;
        const float* s = base + 6 * p;
        xx[p] = f2pack(s[0], s[3]);
        yy[p] = f2pack(s[1], s[4]);
        zz[p] = f2pack(s[2], s[5]);
    }
}

// -------- stats: partial softmax stats per query over one opponent half --------
__global__ void stats_kernel(const float* __restrict__ prd, const float* __restrict__ tgt) {
    extern __shared__ ull sm8[];
    ull* xx = sm8;
    ull* yy = sm8 + NPAIRS_H;
    ull* zz = sm8 + 2 * NPAIRS_H;
    int t = threadIdx.x;
    int b = blockIdx.y;
    int side = blockIdx.z >> 1, half = blockIdx.z & 1;
    const float* qbase = side == 0 ? tgt : prd;
    const float* obase = side == 0 ? prd : tgt;
    int qloc = t / SUBS, sub = t % SUBS;
    int m = blockIdx.x * QPB + qloc;

    fill_pairs(xx, yy, zz, obase + (size_t)b * NPTS * 3 + (size_t)half * HALF * 3, t);
    const float* q = qbase + ((size_t)b * NPTS + m) * 3;
    ull nqx = f2pack(-q[0], -q[0]);
    ull nqy = f2pack(-q[1], -q[1]);
    ull nqz = f2pack(-q[2], -q[2]);
    __syncthreads();

    float mn2 = 1e30f, ZA = 0.f, ZB = 0.f, SuA = 0.f, SuB = 0.f;
#pragma unroll 4
    for (int j = 0; j < PCHUNK_H; j++) {
        int pi = sub + j * SUBS;
        ull dxp = f2add(xx[pi], nqx);
        ull dyp = f2add(yy[pi], nqy);
        ull dzp = f2add(zz[pi], nqz);
        ull d2p = f2mul(dxp, dxp);
        d2p = f2fma(dyp, dyp, d2p);
        d2p = f2fma(dzp, dzp, d2p);
        float d2A, d2B;
        f2unpack(d2p, d2A, d2B);
        mn2 = fminf(mn2, d2A);
        mn2 = fminf(mn2, d2B);
        float argA = sqa(d2A) * NKEXP;
        float argB = sqa(d2B) * NKEXP;
        float pA = ex2(argA);
        float pB = ex2(argB);
        ZA += pA; ZB += pB;
        SuA = fmaf(pA, argA, SuA);
        SuB = fmaf(pB, argB, SuB);
    }
    float Z = ZA + ZB, Su = SuA + SuB;
#pragma unroll
    for (int o = 1; o < SUBS; o <<= 1) {
        mn2 = fminf(mn2, __shfl_xor_sync(0xffffffffu, mn2, o));
        Z += __shfl_xor_sync(0xffffffffu, Z, o);
        Su += __shfl_xor_sync(0xffffffffu, Su, o);
    }
    if (sub == 0) {
        int idx = b * NPTS + m;
        g_Zp[side][half][idx] = Z;
        g_Sup[side][half][idx] = Su;
        g_mnp[side][half][idx] = mn2;
    }
}

// -------- finalize stats: 16384 queries --------
__global__ void stats_fin_kernel() {
    int i = blockIdx.x * blockDim.x + threadIdx.x;   // 0..16383
    int side = i >> 13;
    int q = i & (BN - 1);
    float Z = g_Zp[side][0][q] + g_Zp[side][1][q];
    float Su = g_Sup[side][0][q] + g_Sup[side][1][q];
    float rz = rcp(Z);
    float T = Su * rz * INV_NK;
    float csx = COEF * rz;
    float csy = fmaf(T, INV_TAU, 1.f);
    g_stats[side][q] = make_float2(csx, csy);
    if (side == 0) { g_csx[q] = csx; g_csy[q] = csy; }   // pair-adjacent planes
    float mn = sqrtf(fminf(g_mnp[side][0][q], g_mnp[side][1][q]));
    __shared__ float sh[8];
    float mnS = blockSum(mn, sh);
    float TS = blockSum(T, sh);
    if (threadIdx.x == 0) {
        g_sf_mn[blockIdx.x] = mnS;
        g_sf_T[blockIdx.x] = TS;
    }
}

// -------- grad: packed EMD gradient partials over one target half --------
__global__ void grad_kernel(const float* __restrict__ prd, const float* __restrict__ tgt) {
    extern __shared__ ull sm8[];
    ull* xx = sm8;
    ull* yy = sm8 + NPAIRS_H;
    ull* zz = sm8 + 2 * NPAIRS_H;
    int t = threadIdx.x;
    int b = blockIdx.y;
    int half = blockIdx.z;
    int qloc = t / SUBS, sub = t % SUBS;
    int n = blockIdx.x * QPB + qloc;

    fill_pairs(xx, yy, zz, tgt + (size_t)b * NPTS * 3 + (size_t)half * HALF * 3, t);
    const float* q = prd + ((size_t)b * NPTS + n) * 3;
    ull nqx = f2pack(-q[0], -q[0]);
    ull nqy = f2pack(-q[1], -q[1]);
    ull nqz = f2pack(-q[2], -q[2]);
    float2 rsc = g_stats[1][b * NPTS + n];      // (COEF/Zr, 1 + S/tau)
    float A0 = rsc.x * rsc.y;
    float B0 = rsc.x * INV_TAU;
    ull A0p = f2pack(A0, A0);
    ull nB0p = f2pack(-B0, -B0);
    ull nITp = f2pack(-INV_TAU, -INV_TAU);
    int cbase = (b * NPTS + half * HALF) / 2;   // pair index into cs planes
    const ull* __restrict__ csxp_g = (const ull*)g_csx + cbase;
    const ull* __restrict__ csyp_g = (const ull*)g_csy + cbase;
    __syncthreads();

    ull gxp = 0ull, gyp = 0ull, gzp = 0ull;
#pragma unroll 4
    for (int j = 0; j < PCHUNK_H; j++) {
        int pi = sub + j * SUBS;
        ull csxp = __ldg(&csxp_g[pi]);
        ull csyp = __ldg(&csyp_g[pi]);
        ull dxp = f2add(xx[pi], nqx);
        ull dyp = f2add(yy[pi], nqy);
        ull dzp = f2add(zz[pi], nqz);
        ull d2p = f2mul(dxp, dxp);
        d2p = f2fma(dyp, dyp, d2p);
        d2p = f2fma(dzp, dzp, d2p);
        float d2A, d2B;
        f2unpack(d2p, d2A, d2B);
        float rA = rsq(d2A), rB = rsq(d2B);
        float pA = ex2((d2A * NKEXP) * rA);
        float pB = ex2((d2B * NKEXP) * rB);
        ull t1p = f2fma(csxp, csyp, A0p);       // t1 = csx*csy + A0
        ull nt2p = f2fma(csxp, nITp, nB0p);     // -t2 = -(csx/tau + B0)
        ull rp = f2pack(rA, rB);
        ull pp = f2pack(pA, pB);
        ull innerp = f2fma(t1p, rp, nt2p);      // t1*r - t2
        ull wp = f2mul(pp, innerp);
        gxp = f2fma(wp, dxp, gxp);
        gyp = f2fma(wp, dyp, gyp);
        gzp = f2fma(wp, dzp, gzp);
    }
    float a, bb;
    f2unpack(gxp, a, bb); float gx = a + bb;
    f2unpack(gyp, a, bb); float gy = a + bb;
    f2unpack(gzp, a, bb); float gz = a + bb;
#pragma unroll
    for (int o = 1; o < SUBS; o <<= 1) {
        gx += __shfl_xor_sync(0xffffffffu, gx, o);
        gy += __shfl_xor_sync(0xffffffffu, gy, o);
        gz += __shfl_xor_sync(0xffffffffu, gz, o);
    }
    if (sub == 0) {
        int idx = b * NPTS + n;
        g_gp[half][0][idx] = gx;
        g_gp[half][1][idx] = gy;
        g_gp[half][2][idx] = gz;
    }
}

// -------- finalize grad: 8192 queries --------
__global__ void grad_fin_kernel() {
    int i = blockIdx.x * blockDim.x + threadIdx.x;
    float gx = g_gp[0][0][i] + g_gp[1][0][i];
    float gy = g_gp[0][1][i] + g_gp[1][1][i];
    float gz = g_gp[0][2][i] + g_gp[1][2][i];
    float nrm = sqrtf(fmaf(gx, gx, fmaf(gy, gy, gz * gz)));
    __shared__ float sh[8];
    float vs = blockSum(fabsf(nrm - 1.f), sh);
    if (threadIdx.x == 0) g_gf[blockIdx.x] = vs;
}

// ---------------- final: gather all partials, compute total ----------------
__global__ void final_kernel(float* __restrict__ out, int bp) {
    int t = threadIdx.x;
    float s0 = 0.f, s1 = 0.f, s2 = 0.f, s3 = 0.f, sMn = 0.f, sT = 0.f, sG = 0.f;
    for (int i = t; i < PW_BLOCKS; i += THREADS) {
        s0 += g_pw[0][i]; s1 += g_pw[1][i]; s2 += g_pw[2][i]; s3 += g_pw[3][i];
    }
    if (t < 64) { sMn = g_sf_mn[t]; sT = g_sf_T[t]; }
    if (t < 32) sG = g_gf[t];
    __shared__ float sh[8];
    s0 = blockSum(s0, sh);
    s1 = blockSum(s1, sh);
    s2 = blockSum(s2, sh);
    s3 = blockSum(s3, sh);
    sMn = blockSum(sMn, sh);
    sT = blockSum(sT, sh);
    sG = blockSum(sG, sh);
    if (t == 0) {
        float invBP = 1.f / (float)bp;
        float invBN = 1.f / (float)BN;
        float l1 = s0 * invBP;
        float bce = s1 * invBP;
        float unc = s2 * invBP;
        float nrm = s3 * invBP;
        float cham = sMn * invBN;
        float emd = sT * invBN;
        float gp = sG * invBN;
        float pt = expf(-bce);
        float occ = 0.75f * (1.f - pt) * (1.f - pt) * bce;
        out[0] = l1 + occ + 0.1f * nrm + cham + 0.25f * emd + 0.05f * gp + 0.1f * unc;
    }
}

extern "C" void kernel_launch(void* const* d_in, const int* in_sizes, int n_in,
                              void* d_out, int out_size) {
    const float* sdf_pred   = (const float*)d_in[0];
    const float* sdf_target = (const float*)d_in[1];
    const float* uncertainty = (const float*)d_in[2];
    const float* occ_pred   = (const float*)d_in[3];
    const float* occ_target = (const float*)d_in[4];
    const float* nrm_pred   = (const float*)d_in[5];
    const float* nrm_target = (const float*)d_in[6];
    const float* pc_pred    = (const float*)d_in[7];
    const float* pc_target  = (const float*)d_in[8];
    float* out = (float*)d_out;

    int bp = in_sizes[0];   // B * P = 200000

    pointwise_kernel<<<PW_BLOCKS, THREADS>>>(sdf_pred, sdf_target, uncertainty,
                                             occ_pred, occ_target, nrm_pred, nrm_target, bp);
    dim3 sgrid(NPTS / QPB, BATCH, 4);   // 2 sides x 2 halves
    stats_kernel<<<sgrid, THREADS, TILE_BYTES>>>(pc_pred, pc_target);
    stats_fin_kernel<<<64, THREADS>>>();
    dim3 ggrid(NPTS / QPB, BATCH, 2);   // 2 halves
    grad_kernel<<<ggrid, THREADS, TILE_BYTES>>>(pc_pred, pc_target);
    grad_fin_kernel<<<32, THREADS>>>();
    final_kernel<<<1, THREADS>>>(out, bp);
}